// round 3
// baseline (speedup 1.0000x reference)
#include <cuda_runtime.h>
#include <cuda_bf16.h>
#include <cstdint>
#include <cstddef>

#define Msz 4096
#define Ksz 4096
#define Nsz 4096
#define TKC 128
#define NCHUNK (Ksz / TKC)   // 32

// Scratch (static device globals: allocation-free at runtime)
__device__ int8_t  g_Xb[(size_t)Msz * Ksz];   // x as s8, [M,K] row-major
__device__ uint8_t g_Yt[(size_t)Nsz * Ksz];   // y^T as u8, [N,K] row-major
__device__ int g_R[Msz];                      // rowsum of x (int)
__device__ int g_C[Nsz];                      // colsum of y (int)

__device__ __forceinline__ uint32_t smem_u32(const void* p) {
    uint32_t a;
    asm("{ .reg .u64 t; cvta.to.shared.u64 t, %1; cvt.u32.u64 %0, t; }" : "=r"(a) : "l"(p));
    return a;
}

#define SWZ(off) ((off) ^ (((off) >> 3) & 0x70))

// ---------------- Prep kernels ----------------
__global__ void zero_c_kernel() {
    int i = blockIdx.x * blockDim.x + threadIdx.x;
    if (i < Nsz) g_C[i] = 0;
}

// One block per row of x: fp32 -> s8 convert + integer rowsum
__global__ void prep_x_kernel(const float* __restrict__ x) {
    int m = blockIdx.x;
    const float4* xr = (const float4*)(x + (size_t)m * Ksz);
    uint32_t* dst = (uint32_t*)(g_Xb + (size_t)m * Ksz);
    int sum = 0;
    for (int i = threadIdx.x; i < Ksz / 4; i += 256) {
        float4 v = xr[i];
        int v0 = (int)v.x, v1 = (int)v.y, v2 = (int)v.z, v3 = (int)v.w;
        sum += (v0 + v1) + (v2 + v3);
        dst[i] = (uint32_t)(v0 & 0xFF) | ((uint32_t)(v1 & 0xFF) << 8) |
                 ((uint32_t)(v2 & 0xFF) << 16) | ((uint32_t)(v3 & 0xFF) << 24);
    }
    #pragma unroll
    for (int o = 16; o; o >>= 1) sum += __shfl_xor_sync(0xFFFFFFFFu, sum, o);
    __shared__ int ws[8];
    if ((threadIdx.x & 31) == 0) ws[threadIdx.x >> 5] = sum;
    __syncthreads();
    if (threadIdx.x == 0) {
        int t = 0;
        #pragma unroll
        for (int w = 0; w < 8; w++) t += ws[w];
        g_R[m] = t;
    }
}

// 32x32 tile transpose of y into Yt (u8) + integer colsum via atomicAdd
__global__ void prep_y_kernel(const float* __restrict__ y) {
    __shared__ float tile[32][33];
    int n0 = blockIdx.x * 32, k0 = blockIdx.y * 32;
    int tx = threadIdx.x, ty = threadIdx.y;  // 32 x 8
    #pragma unroll
    for (int r = 0; r < 4; r++)
        tile[ty + r * 8][tx] = y[(size_t)(k0 + ty + r * 8) * Nsz + n0 + tx];
    __syncthreads();
    // thread (tx,ty): row n = tx, k-group ty -> pack 4 k-bytes into one u32 store
    {
        int b0 = (int)tile[ty * 4 + 0][tx];
        int b1 = (int)tile[ty * 4 + 1][tx];
        int b2 = (int)tile[ty * 4 + 2][tx];
        int b3 = (int)tile[ty * 4 + 3][tx];
        uint32_t packed = (uint32_t)(b0 & 0xFF) | ((uint32_t)(b1 & 0xFF) << 8) |
                          ((uint32_t)(b2 & 0xFF) << 16) | ((uint32_t)(b3 & 0xFF) << 24);
        ((uint32_t*)(g_Yt + (size_t)(n0 + tx) * Ksz + k0))[ty] = packed;
    }
    if (ty == 0) {
        int s = 0;
        #pragma unroll
        for (int i = 0; i < 32; i++) s += (int)tile[i][tx];
        atomicAdd(&g_C[n0 + tx], s);
    }
}

// ---------------- GEMM kernel (mma.sync s8xu8 IMMA, cp.async double-buffer) ----------------
// Dynamic SMEM: A0 [0,16K), A1 [16K,32K), B0 [32K,48K), B1 [48K,64K)
#define ABYTES 16384
#define SMEM_TOTAL (4 * ABYTES)   // 64 KB

__device__ __forceinline__ void load_chunk(uint32_t abuf, uint32_t bbuf, int tid,
                                           int m0, int n0, int k0) {
    const char* xb = (const char*)g_Xb;
    const char* yb = (const char*)g_Yt;
    #pragma unroll
    for (int e = 0; e < 4; e++) {
        int idx = tid + e * 256;
        int row = idx >> 3;      // 0..127
        int grp = idx & 7;       // 16B group within 128B row
        uint32_t soff = SWZ((uint32_t)(row * 128 + grp * 16));
        size_t ea = (size_t)(m0 + row) * Ksz + (size_t)(k0 + grp * 16);
        asm volatile("cp.async.cg.shared.global [%0], [%1], 16;"
                     :: "r"(abuf + soff), "l"(xb + ea) : "memory");
        size_t eb = (size_t)(n0 + row) * Ksz + (size_t)(k0 + grp * 16);
        asm volatile("cp.async.cg.shared.global [%0], [%1], 16;"
                     :: "r"(bbuf + soff), "l"(yb + eb) : "memory");
    }
    asm volatile("cp.async.commit_group;" ::: "memory");
}

__global__ void __launch_bounds__(256, 2) gemm_kernel(float* __restrict__ out) {
    extern __shared__ char smem[];
    uint32_t sb = smem_u32(smem);
    int tid = threadIdx.x;
    int lane = tid & 31;
    int wid = tid >> 5;
    int m0 = blockIdx.y * 128;
    int n0 = blockIdx.x * 128;
    int wm = (wid >> 1) * 32;   // 4 warps in M
    int wn = (wid & 1) * 64;    // 2 warps in N

    int acc[2][8][4];
    #pragma unroll
    for (int i = 0; i < 2; i++)
        #pragma unroll
        for (int j = 0; j < 8; j++)
            #pragma unroll
            for (int q = 0; q < 4; q++) acc[i][j][q] = 0;

    // ldmatrix address components — byte-identical to the verified bf16 layout.
    // A x4 ordering: {m0-7 B0-15}{m8-15 B0-15}{m0-7 B16-31}{m8-15 B16-31} per k32 step
    int a_row_lo = wm + (lane & 15);                  // + mi*16
    int a_kg_off = (lane >> 4);                       // + ks*2 (16B groups)
    // B x4 ordering: {n0-7 B0-15}{n0-7 B16-31}{n8-15 B0-15}{n8-15 B16-31}
    int b_row_lo = wn + ((lane >> 4) << 3) + (lane & 7);   // + nj4*16
    int b_kg_off = ((lane >> 3) & 1);                      // + ks*2

    load_chunk(sb, sb + 2 * ABYTES, tid, m0, n0, 0);

    for (int c = 0; c < NCHUNK; c++) {
        int b = c & 1;
        if (c + 1 < NCHUNK) {
            load_chunk(sb + (uint32_t)(b ^ 1) * ABYTES,
                       sb + 2 * ABYTES + (uint32_t)(b ^ 1) * ABYTES,
                       tid, m0, n0, (c + 1) * TKC);
            asm volatile("cp.async.wait_group 1;" ::: "memory");
        } else {
            asm volatile("cp.async.wait_group 0;" ::: "memory");
        }
        __syncthreads();

        uint32_t abase = sb + (uint32_t)b * ABYTES;
        uint32_t bbase = sb + 2 * ABYTES + (uint32_t)b * ABYTES;

        #pragma unroll
        for (int ks = 0; ks < 4; ks++) {   // k32 per step, 4 steps = K 128
            uint32_t afr[2][4], bfr[4][4];
            #pragma unroll
            for (int mi = 0; mi < 2; mi++) {
                int row = a_row_lo + mi * 16;
                int kg = ks * 2 + a_kg_off;
                uint32_t addr = abase + SWZ((uint32_t)(row * 128 + kg * 16));
                asm volatile("ldmatrix.sync.aligned.m8n8.x4.shared.b16 {%0,%1,%2,%3}, [%4];"
                             : "=r"(afr[mi][0]), "=r"(afr[mi][1]),
                               "=r"(afr[mi][2]), "=r"(afr[mi][3])
                             : "r"(addr));
            }
            #pragma unroll
            for (int nj4 = 0; nj4 < 4; nj4++) {
                int row = b_row_lo + nj4 * 16;
                int kg = ks * 2 + b_kg_off;
                uint32_t addr = bbase + SWZ((uint32_t)(row * 128 + kg * 16));
                asm volatile("ldmatrix.sync.aligned.m8n8.x4.shared.b16 {%0,%1,%2,%3}, [%4];"
                             : "=r"(bfr[nj4][0]), "=r"(bfr[nj4][1]),
                               "=r"(bfr[nj4][2]), "=r"(bfr[nj4][3])
                             : "r"(addr));
            }
            #pragma unroll
            for (int mi = 0; mi < 2; mi++) {
                #pragma unroll
                for (int nj = 0; nj < 8; nj++) {
                    uint32_t b0 = bfr[nj >> 1][(nj & 1) * 2 + 0];
                    uint32_t b1 = bfr[nj >> 1][(nj & 1) * 2 + 1];
                    asm volatile(
                        "mma.sync.aligned.m16n8k32.row.col.s32.s8.u8.s32 "
                        "{%0,%1,%2,%3}, {%4,%5,%6,%7}, {%8,%9}, {%0,%1,%2,%3};"
                        : "+r"(acc[mi][nj][0]), "+r"(acc[mi][nj][1]),
                          "+r"(acc[mi][nj][2]), "+r"(acc[mi][nj][3])
                        : "r"(afr[mi][0]), "r"(afr[mi][1]),
                          "r"(afr[mi][2]), "r"(afr[mi][3]),
                          "r"(b0), "r"(b1));
                }
            }
        }
        __syncthreads();
    }

    // Epilogue: out = 7.5e-4 * (Z - 160*R[m] + 66*C[n] - 4096*66*160)  — exact ints
    const float s = 7.5e-4f;
    #pragma unroll
    for (int mi = 0; mi < 2; mi++) {
        int r0 = m0 + wm + mi * 16 + (lane >> 2);
        int r1 = r0 + 8;
        int bias0 = -160 * g_R[r0] - 43253760;
        int bias1 = -160 * g_R[r1] - 43253760;
        #pragma unroll
        for (int nj = 0; nj < 8; nj++) {
            int col = n0 + wn + nj * 8 + 2 * (lane & 3);
            int2 cv = *(const int2*)(g_C + col);
            float2 v0, v1;
            v0.x = (float)(acc[mi][nj][0] + bias0 + 66 * cv.x) * s;
            v0.y = (float)(acc[mi][nj][1] + bias0 + 66 * cv.y) * s;
            v1.x = (float)(acc[mi][nj][2] + bias1 + 66 * cv.x) * s;
            v1.y = (float)(acc[mi][nj][3] + bias1 + 66 * cv.y) * s;
            *(float2*)(out + (size_t)r0 * Nsz + col) = v0;
            *(float2*)(out + (size_t)r1 * Nsz + col) = v1;
        }
    }
}

// ---------------- Launch ----------------
extern "C" void kernel_launch(void* const* d_in, const int* in_sizes, int n_in,
                              void* d_out, int out_size) {
    const float* x = (const float*)d_in[0];   // [M, K] fp32 (int-valued)
    const float* y = (const float*)d_in[1];   // [K, N] fp32 (int-valued)
    float* out = (float*)d_out;               // [M, N] fp32

    cudaFuncSetAttribute(gemm_kernel, cudaFuncAttributeMaxDynamicSharedMemorySize, SMEM_TOTAL);

    zero_c_kernel<<<16, 256>>>();
    prep_x_kernel<<<Msz, 256>>>(x);
    prep_y_kernel<<<dim3(Nsz / 32, Ksz / 32), dim3(32, 8)>>>(y);
    gemm_kernel<<<dim3(Nsz / 128, Msz / 128), 256, SMEM_TOTAL>>>(out);
}

// round 4
// speedup vs baseline: 2.8831x; 2.8831x over previous
#include <cuda_runtime.h>
#include <cuda_bf16.h>
#include <cstdint>
#include <cstddef>

#define Msz 4096
#define Ksz 4096
#define Nsz 4096
#define TKC 64
#define NCHUNK (Ksz / TKC)   // 64

// Scratch (static device globals: allocation-free at runtime)
__device__ __nv_bfloat16 g_Xb[(size_t)Msz * Ksz];   // x as bf16, [M,K] row-major
__device__ __nv_bfloat16 g_Yt[(size_t)Nsz * Ksz];   // y^T as bf16, [N,K] row-major
__device__ float g_R[Msz];                          // rowsum of x
__device__ float g_C[Nsz];                          // colsum of y

__device__ __forceinline__ uint32_t smem_u32(const void* p) {
    uint32_t a;
    asm("{ .reg .u64 t; cvta.to.shared.u64 t, %1; cvt.u32.u64 %0, t; }" : "=r"(a) : "l"(p));
    return a;
}

#define SWZ(off) ((off) ^ (((off) >> 3) & 0x70))

// ---------------- Prep kernels ----------------
__global__ void zero_c_kernel() {
    int i = blockIdx.x * blockDim.x + threadIdx.x;
    if (i < Nsz) g_C[i] = 0.0f;
}

// One block per row of x: fp32 -> bf16 convert + rowsum
__global__ void prep_x_kernel(const float* __restrict__ x) {
    int m = blockIdx.x;
    const float4* xr = (const float4*)(x + (size_t)m * Ksz);
    uint2* dst = (uint2*)(g_Xb + (size_t)m * Ksz);
    float sum = 0.0f;
    for (int i = threadIdx.x; i < Ksz / 4; i += 256) {
        float4 v = xr[i];
        sum += (v.x + v.y) + (v.z + v.w);
        __nv_bfloat162 lo = __floats2bfloat162_rn(v.x, v.y);
        __nv_bfloat162 hi = __floats2bfloat162_rn(v.z, v.w);
        uint2 u;
        u.x = *reinterpret_cast<uint32_t*>(&lo);
        u.y = *reinterpret_cast<uint32_t*>(&hi);
        dst[i] = u;
    }
    #pragma unroll
    for (int o = 16; o; o >>= 1) sum += __shfl_xor_sync(0xFFFFFFFFu, sum, o);
    __shared__ float ws[8];
    if ((threadIdx.x & 31) == 0) ws[threadIdx.x >> 5] = sum;
    __syncthreads();
    if (threadIdx.x == 0) {
        float t = 0.0f;
        #pragma unroll
        for (int w = 0; w < 8; w++) t += ws[w];
        g_R[m] = t;
    }
}

// 32x32 tile transpose of y into Yt (bf16) + colsum via atomicAdd (partials exact ints)
__global__ void prep_y_kernel(const float* __restrict__ y) {
    __shared__ float tile[32][33];
    int n0 = blockIdx.x * 32, k0 = blockIdx.y * 32;
    int tx = threadIdx.x, ty = threadIdx.y;  // 32 x 8
    #pragma unroll
    for (int r = 0; r < 4; r++)
        tile[ty + r * 8][tx] = y[(size_t)(k0 + ty + r * 8) * Nsz + n0 + tx];
    __syncthreads();
    #pragma unroll
    for (int r = 0; r < 4; r++) {
        int row = ty + r * 8;
        g_Yt[(size_t)(n0 + row) * Ksz + k0 + tx] = __float2bfloat16(tile[tx][row]);
    }
    if (ty == 0) {
        float s = 0.0f;
        #pragma unroll
        for (int i = 0; i < 32; i++) s += tile[i][tx];
        atomicAdd(&g_C[n0 + tx], s);
    }
}

// ---------------- GEMM kernel (bf16 mma.sync, 3-stage cp.async pipeline) ----------------
// Dynamic SMEM: stage s at s*32K: A [0,16K), B [16K,32K). 3 stages = 96 KB.
#define ABYTES 16384
#define STAGEBYTES (2 * ABYTES)
#define NSTAGE 3
#define SMEM_TOTAL (NSTAGE * STAGEBYTES)   // 98304

__device__ __forceinline__ void load_chunk(uint32_t stage_base, int tid,
                                           int m0, int n0, int k0) {
    uint32_t abuf = stage_base;
    uint32_t bbuf = stage_base + ABYTES;
    const char* xb = (const char*)g_Xb;
    const char* yb = (const char*)g_Yt;
    #pragma unroll
    for (int e = 0; e < 4; e++) {
        int idx = tid + e * 256;
        int row = idx >> 3;      // 0..127
        int grp = idx & 7;       // 16B group (8 bf16) within 128B row
        uint32_t soff = SWZ((uint32_t)(row * 128 + grp * 16));
        size_t ea = ((size_t)(m0 + row) * Ksz + (size_t)(k0 + grp * 8)) * 2;
        asm volatile("cp.async.cg.shared.global [%0], [%1], 16;"
                     :: "r"(abuf + soff), "l"(xb + ea) : "memory");
        size_t eb = ((size_t)(n0 + row) * Ksz + (size_t)(k0 + grp * 8)) * 2;
        asm volatile("cp.async.cg.shared.global [%0], [%1], 16;"
                     :: "r"(bbuf + soff), "l"(yb + eb) : "memory");
    }
    asm volatile("cp.async.commit_group;" ::: "memory");
}

__global__ void __launch_bounds__(256, 2) gemm_kernel(float* __restrict__ out) {
    extern __shared__ char smem[];
    uint32_t sb = smem_u32(smem);
    int tid = threadIdx.x;
    int lane = tid & 31;
    int wid = tid >> 5;
    int m0 = blockIdx.y * 128;
    int n0 = blockIdx.x * 128;
    int wm = (wid >> 1) * 32;   // 4 warps in M
    int wn = (wid & 1) * 64;    // 2 warps in N

    float acc[2][8][4];
    #pragma unroll
    for (int i = 0; i < 2; i++)
        #pragma unroll
        for (int j = 0; j < 8; j++)
            #pragma unroll
            for (int q = 0; q < 4; q++) acc[i][j][q] = 0.0f;

    // ldmatrix address components (verified in round 2)
    int a_row_lo = wm + (lane & 15);                  // + mi*16
    int a_kg_off = (lane >> 4);                       // + ks*2
    int b_row_lo = wn + ((lane >> 4) << 3) + (lane & 7);   // + nj4*16
    int b_kg_off = ((lane >> 3) & 1);                      // + ks*2

    // Prologue: prefetch chunks 0 and 1
    load_chunk(sb + 0 * STAGEBYTES, tid, m0, n0, 0);
    load_chunk(sb + 1 * STAGEBYTES, tid, m0, n0, TKC);

    int stage = 0;
    for (int c = 0; c < NCHUNK; c++) {
        // chunk c's group must be complete
        if (c + 1 < NCHUNK) {
            asm volatile("cp.async.wait_group 1;" ::: "memory");
        } else {
            asm volatile("cp.async.wait_group 0;" ::: "memory");
        }
        __syncthreads();   // data visible to all; prior iteration's reads sealed

        if (c + 2 < NCHUNK) {
            int ls = stage + 2;
            if (ls >= NSTAGE) ls -= NSTAGE;
            load_chunk(sb + (uint32_t)ls * STAGEBYTES, tid, m0, n0, (c + 2) * TKC);
        }

        uint32_t abase = sb + (uint32_t)stage * STAGEBYTES;
        uint32_t bbase = abase + ABYTES;

        #pragma unroll
        for (int ks = 0; ks < 4; ks++) {
            uint32_t afr[2][4], bfr[4][4];
            #pragma unroll
            for (int mi = 0; mi < 2; mi++) {
                int row = a_row_lo + mi * 16;
                int kg = ks * 2 + a_kg_off;
                uint32_t addr = abase + SWZ((uint32_t)(row * 128 + kg * 16));
                asm volatile("ldmatrix.sync.aligned.m8n8.x4.shared.b16 {%0,%1,%2,%3}, [%4];"
                             : "=r"(afr[mi][0]), "=r"(afr[mi][1]),
                               "=r"(afr[mi][2]), "=r"(afr[mi][3])
                             : "r"(addr));
            }
            #pragma unroll
            for (int nj4 = 0; nj4 < 4; nj4++) {
                int row = b_row_lo + nj4 * 16;
                int kg = ks * 2 + b_kg_off;
                uint32_t addr = bbase + SWZ((uint32_t)(row * 128 + kg * 16));
                asm volatile("ldmatrix.sync.aligned.m8n8.x4.shared.b16 {%0,%1,%2,%3}, [%4];"
                             : "=r"(bfr[nj4][0]), "=r"(bfr[nj4][1]),
                               "=r"(bfr[nj4][2]), "=r"(bfr[nj4][3])
                             : "r"(addr));
            }
            #pragma unroll
            for (int mi = 0; mi < 2; mi++) {
                #pragma unroll
                for (int nj = 0; nj < 8; nj++) {
                    uint32_t b0 = bfr[nj >> 1][(nj & 1) * 2 + 0];
                    uint32_t b1 = bfr[nj >> 1][(nj & 1) * 2 + 1];
                    asm volatile(
                        "mma.sync.aligned.m16n8k16.row.col.f32.bf16.bf16.f32 "
                        "{%0,%1,%2,%3}, {%4,%5,%6,%7}, {%8,%9}, {%0,%1,%2,%3};"
                        : "+f"(acc[mi][nj][0]), "+f"(acc[mi][nj][1]),
                          "+f"(acc[mi][nj][2]), "+f"(acc[mi][nj][3])
                        : "r"(afr[mi][0]), "r"(afr[mi][1]),
                          "r"(afr[mi][2]), "r"(afr[mi][3]),
                          "r"(b0), "r"(b1));
                }
            }
        }
        stage = (stage + 1 == NSTAGE) ? 0 : stage + 1;
    }

    // Epilogue: out = 7.5e-4 * (Z - 160*R[m] + 66*C[n] - 4096*66*160)
    const float s = 7.5e-4f;
    #pragma unroll
    for (int mi = 0; mi < 2; mi++) {
        int r0 = m0 + wm + mi * 16 + (lane >> 2);
        int r1 = r0 + 8;
        float bias0 = fmaf(-160.0f, g_R[r0], -43253760.0f);
        float bias1 = fmaf(-160.0f, g_R[r1], -43253760.0f);
        #pragma unroll
        for (int nj = 0; nj < 8; nj++) {
            int col = n0 + wn + nj * 8 + 2 * (lane & 3);
            float2 cv = *(const float2*)(g_C + col);
            float2 v0, v1;
            v0.x = (acc[mi][nj][0] + bias0 + 66.0f * cv.x) * s;
            v0.y = (acc[mi][nj][1] + bias0 + 66.0f * cv.y) * s;
            v1.x = (acc[mi][nj][2] + bias1 + 66.0f * cv.x) * s;
            v1.y = (acc[mi][nj][3] + bias1 + 66.0f * cv.y) * s;
            *(float2*)(out + (size_t)r0 * Nsz + col) = v0;
            *(float2*)(out + (size_t)r1 * Nsz + col) = v1;
        }
    }
}

// ---------------- Launch ----------------
extern "C" void kernel_launch(void* const* d_in, const int* in_sizes, int n_in,
                              void* d_out, int out_size) {
    const float* x = (const float*)d_in[0];   // [M, K] fp32 (int-valued)
    const float* y = (const float*)d_in[1];   // [K, N] fp32 (int-valued)
    float* out = (float*)d_out;               // [M, N] fp32

    cudaFuncSetAttribute(gemm_kernel, cudaFuncAttributeMaxDynamicSharedMemorySize, SMEM_TOTAL);

    zero_c_kernel<<<16, 256>>>();
    prep_x_kernel<<<Msz, 256>>>(x);
    prep_y_kernel<<<dim3(Nsz / 32, Ksz / 32), dim3(32, 8)>>>(y);
    gemm_kernel<<<dim3(Nsz / 128, Msz / 128), 256, SMEM_TOTAL>>>(out);
}